// round 1
// baseline (speedup 1.0000x reference)
#include <cuda_runtime.h>
#include <math.h>

#define BB 2
#define EE 512
#define NN 4096
#define MM 4096

// Scratch (static __device__ — allocation-free per harness rules)
__device__ float g_Q[BB * NN * EE];   // [b][n][e] 16 MB
__device__ float g_K[BB * MM * EE];   // [b][m][e] 16 MB
__device__ float g_kk[BB * MM];       // ||k||^2

// ---------------------------------------------------------------------------
// Projection: Y[b][n][f] = sum_e X[b][e][n] * W[f][e] + bias[f]
// Block tile 64(n) x 128(f), 256 threads, per-thread 4x8, K-chunk 32.
// ---------------------------------------------------------------------------
__global__ __launch_bounds__(256) void proj_kernel(
    const float* __restrict__ X, const float* __restrict__ W,
    const float* __restrict__ bias, int which)
{
    float* __restrict__ Y = which ? g_K : g_Q;
    __shared__ float Xs[32][64];    // [e][n]
    __shared__ float Ws[32][128];   // [e][f]

    const int tid = threadIdx.x;
    const int tx = tid & 15, ty = tid >> 4;
    const int n0 = blockIdx.x * 64;
    const int f0 = blockIdx.y * 128;
    const int b  = blockIdx.z;

    float acc[4][8];
#pragma unroll
    for (int i = 0; i < 4; ++i)
#pragma unroll
        for (int j = 0; j < 8; ++j) acc[i][j] = 0.f;

    const float* Xb = X + (size_t)b * EE * NN;

    for (int e0 = 0; e0 < EE; e0 += 32) {
        // Xs: 32 e-rows x 64 n-cols, direct copy (X is n-contiguous)
        {
            const int r = tid >> 3;           // 0..31
            const int c = (tid & 7) * 8;      // 0..56
            const float4* s4 = (const float4*)(Xb + (size_t)(e0 + r) * NN + n0 + c);
            float4 v0 = s4[0], v1 = s4[1];
            *(float4*)&Xs[r][c]     = v0;
            *(float4*)&Xs[r][c + 4] = v1;
        }
        // Ws: transpose 128 f-rows x 32 e-cols -> [e][f]
        {
            const int f  = tid >> 1;          // 0..127
            const int eo = (tid & 1) * 16;    // 0 / 16
            const float4* w4 = (const float4*)(W + (size_t)(f0 + f) * EE + e0 + eo);
#pragma unroll
            for (int k = 0; k < 4; ++k) {
                float4 v = w4[k];
                Ws[eo + 4 * k + 0][f] = v.x;
                Ws[eo + 4 * k + 1][f] = v.y;
                Ws[eo + 4 * k + 2][f] = v.z;
                Ws[eo + 4 * k + 3][f] = v.w;
            }
        }
        __syncthreads();
#pragma unroll 8
        for (int e = 0; e < 32; ++e) {
            float4 a  = *(const float4*)&Xs[e][ty * 4];
            float4 b0 = *(const float4*)&Ws[e][tx * 4];
            float4 b1 = *(const float4*)&Ws[e][64 + tx * 4];
            float av[4] = {a.x, a.y, a.z, a.w};
            float bv[8] = {b0.x, b0.y, b0.z, b0.w, b1.x, b1.y, b1.z, b1.w};
#pragma unroll
            for (int i = 0; i < 4; ++i)
#pragma unroll
                for (int j = 0; j < 8; ++j)
                    acc[i][j] = fmaf(av[i], bv[j], acc[i][j]);
        }
        __syncthreads();
    }

    float4 bs0 = *(const float4*)(bias + f0 + tx * 4);
    float4 bs1 = *(const float4*)(bias + f0 + 64 + tx * 4);
#pragma unroll
    for (int i = 0; i < 4; ++i) {
        const int n = n0 + ty * 4 + i;
        float4 o0 = make_float4(acc[i][0] + bs0.x, acc[i][1] + bs0.y,
                                acc[i][2] + bs0.z, acc[i][3] + bs0.w);
        float4 o1 = make_float4(acc[i][4] + bs1.x, acc[i][5] + bs1.y,
                                acc[i][6] + bs1.z, acc[i][7] + bs1.w);
        float* yr = Y + ((size_t)b * NN + n) * EE + f0;
        *(float4*)(yr + tx * 4)      = o0;
        *(float4*)(yr + 64 + tx * 4) = o1;
    }
}

// ---------------------------------------------------------------------------
// kk[b][m] = sum_f K[b][m][f]^2   (one warp per row)
// ---------------------------------------------------------------------------
__global__ __launch_bounds__(256) void kk_kernel()
{
    const int row  = blockIdx.x * 8 + (threadIdx.x >> 5);
    const int lane = threadIdx.x & 31;
    const float4* kr = (const float4*)(g_K + (size_t)row * EE);
    float s = 0.f;
#pragma unroll
    for (int j = 0; j < 4; ++j) {
        float4 v = kr[lane + j * 32];
        s += v.x * v.x + v.y * v.y + v.z * v.z + v.w * v.w;
    }
#pragma unroll
    for (int off = 16; off; off >>= 1) s += __shfl_xor_sync(0xffffffffu, s, off);
    if (lane == 0) g_kk[row] = s;
}

// ---------------------------------------------------------------------------
// Flash attention: logits = 2 Q K^T - kk, online softmax, O = scores @ tgt^T
// 64 n-rows per CTA; whole Q tile (64x512) resident in SMEM transposed;
// K streamed in 32-e chunks, register double-buffered.
// ---------------------------------------------------------------------------
__global__ __launch_bounds__(256) void attn_kernel(
    const float* __restrict__ tgt, float* __restrict__ out_corr)
{
    extern __shared__ float sm[];
    float* Qs   = sm;                        // [512][64]
    float* Ks   = sm + EE * 64;              // [32][128]
    float* kks  = Ks + 32 * 128;             // [128]
    float* tgts = kks + 128;                 // [3][128]

    const int tid = threadIdx.x;
    const int tx = tid & 15, ty = tid >> 4;
    const int n0 = blockIdx.x * 64;
    const int b  = blockIdx.y;

    // Load Q tile transposed: Qs[e][n]
    {
        const int r  = tid >> 2;             // 0..63
        const int e0 = (tid & 3) * 128;
        const float4* q4 = (const float4*)(g_Q + ((size_t)b * NN + n0 + r) * EE + e0);
#pragma unroll 8
        for (int k = 0; k < 32; ++k) {
            float4 v = q4[k];
            const int e = e0 + 4 * k;
            Qs[(e + 0) * 64 + r] = v.x;
            Qs[(e + 1) * 64 + r] = v.y;
            Qs[(e + 2) * 64 + r] = v.z;
            Qs[(e + 3) * 64 + r] = v.w;
        }
    }

    float st_m[4], st_l[4], st_o[4][3];
#pragma unroll
    for (int i = 0; i < 4; ++i) {
        st_m[i] = -1e30f; st_l[i] = 0.f;
        st_o[i][0] = st_o[i][1] = st_o[i][2] = 0.f;
    }

    const float* Kb   = g_K + (size_t)b * MM * EE;
    const float* kkb  = g_kk + b * MM;
    const float* tgtb = tgt + (size_t)b * 3 * MM;

    const int mrow = tid >> 1;               // 0..127
    const int eoff = (tid & 1) * 16;         // 0 / 16

    for (int m0 = 0; m0 < MM; m0 += 128) {
        __syncthreads();                     // protect kks/tgts/Ks from prior readers
        if (tid < 128) kks[tid] = kkb[m0 + tid];
        for (int t = tid; t < 384; t += 256)
            tgts[t] = tgtb[(t >> 7) * MM + m0 + (t & 127)];

        float acc[4][8];
#pragma unroll
        for (int i = 0; i < 4; ++i)
#pragma unroll
            for (int j = 0; j < 8; ++j) acc[i][j] = 0.f;

        // prefetch chunk 0
        float4 rk[4];
        {
            const float* kb2 = Kb + (size_t)(m0 + mrow) * EE + eoff;
#pragma unroll
            for (int k = 0; k < 4; ++k) rk[k] = *(const float4*)(kb2 + 4 * k);
        }

        for (int c = 0; c < 16; ++c) {
            __syncthreads();                 // prior compute done; smem fills visible
#pragma unroll
            for (int k = 0; k < 4; ++k) {
                const int e = eoff + 4 * k;
                Ks[(e + 0) * 128 + mrow] = rk[k].x;
                Ks[(e + 1) * 128 + mrow] = rk[k].y;
                Ks[(e + 2) * 128 + mrow] = rk[k].z;
                Ks[(e + 3) * 128 + mrow] = rk[k].w;
            }
            __syncthreads();
            if (c < 15) {
                const float* kb2 = Kb + (size_t)(m0 + mrow) * EE + (c + 1) * 32 + eoff;
#pragma unroll
                for (int k = 0; k < 4; ++k) rk[k] = *(const float4*)(kb2 + 4 * k);
            }
#pragma unroll 8
            for (int e = 0; e < 32; ++e) {
                float4 a  = *(const float4*)&Qs[(c * 32 + e) * 64 + ty * 4];
                float4 b0 = *(const float4*)&Ks[e * 128 + tx * 4];
                float4 b1 = *(const float4*)&Ks[e * 128 + 64 + tx * 4];
                float av[4] = {a.x, a.y, a.z, a.w};
                float bv[8] = {b0.x, b0.y, b0.z, b0.w, b1.x, b1.y, b1.z, b1.w};
#pragma unroll
                for (int i = 0; i < 4; ++i)
#pragma unroll
                    for (int j = 0; j < 8; ++j)
                        acc[i][j] = fmaf(av[i], bv[j], acc[i][j]);
            }
        }

        // Online softmax update (per-thread partials; 8 m-cols per thread)
#pragma unroll
        for (int i = 0; i < 4; ++i) {
            float lg[8];
            float lmax = -1e30f;
#pragma unroll
            for (int j = 0; j < 8; ++j) {
                const int mc = (j < 4) ? tx * 4 + j : 64 + tx * 4 + (j - 4);
                lg[j] = 2.f * acc[i][j] - kks[mc];
                lmax = fmaxf(lmax, lg[j]);
            }
            const float nm = fmaxf(st_m[i], lmax);
            const float sc = __expf(st_m[i] - nm);
            st_l[i] *= sc;
            st_o[i][0] *= sc; st_o[i][1] *= sc; st_o[i][2] *= sc;
#pragma unroll
            for (int j = 0; j < 8; ++j) {
                const int mc = (j < 4) ? tx * 4 + j : 64 + tx * 4 + (j - 4);
                const float p = __expf(lg[j] - nm);
                st_l[i] += p;
                st_o[i][0] = fmaf(p, tgts[mc],       st_o[i][0]);
                st_o[i][1] = fmaf(p, tgts[128 + mc], st_o[i][1]);
                st_o[i][2] = fmaf(p, tgts[256 + mc], st_o[i][2]);
            }
            st_m[i] = nm;
        }
    }

    // Merge the 16 per-row partial states (lanes tx=0..15, width-16 shuffles)
#pragma unroll
    for (int i = 0; i < 4; ++i) {
#pragma unroll
        for (int off = 8; off; off >>= 1) {
            float om = __shfl_xor_sync(0xffffffffu, st_m[i],    off, 16);
            float ol = __shfl_xor_sync(0xffffffffu, st_l[i],    off, 16);
            float o0 = __shfl_xor_sync(0xffffffffu, st_o[i][0], off, 16);
            float o1 = __shfl_xor_sync(0xffffffffu, st_o[i][1], off, 16);
            float o2 = __shfl_xor_sync(0xffffffffu, st_o[i][2], off, 16);
            const float nm = fmaxf(st_m[i], om);
            const float sa = __expf(st_m[i] - nm);
            const float sb = __expf(om - nm);
            st_l[i]    = st_l[i]    * sa + ol * sb;
            st_o[i][0] = st_o[i][0] * sa + o0 * sb;
            st_o[i][1] = st_o[i][1] * sa + o1 * sb;
            st_o[i][2] = st_o[i][2] * sa + o2 * sb;
            st_m[i] = nm;
        }
        if (tx == 0) {
            const int n = n0 + ty * 4 + i;
            const float inv = 1.f / st_l[i];
            out_corr[((size_t)b * 3 + 0) * NN + n] = st_o[i][0] * inv;
            out_corr[((size_t)b * 3 + 1) * NN + n] = st_o[i][1] * inv;
            out_corr[((size_t)b * 3 + 2) * NN + n] = st_o[i][2] * inv;
        }
    }
}

// ---------------------------------------------------------------------------
__global__ void copy_src_kernel(const float* __restrict__ src, float* __restrict__ out)
{
    const int i = blockIdx.x * 256 + threadIdx.x;
    if (i < BB * 3 * NN) out[i] = src[i];
}

// ---------------------------------------------------------------------------
extern "C" void kernel_launch(void* const* d_in, const int* in_sizes, int n_in,
                              void* d_out, int out_size)
{
    const float* src_emb = (const float*)d_in[0];
    const float* tgt_emb = (const float*)d_in[1];
    const float* src     = (const float*)d_in[2];
    const float* tgt     = (const float*)d_in[3];
    const float* Wq      = (const float*)d_in[4];
    const float* bq      = (const float*)d_in[5];
    const float* Wk      = (const float*)d_in[6];
    const float* bk      = (const float*)d_in[7];
    float* out = (float*)d_out;

    const int corr_elems = BB * 3 * NN;
    const bool tuple_out = (out_size >= 2 * corr_elems);
    float* corr_out = tuple_out ? (out + corr_elems) : out;

    dim3 pg(NN / 64, EE / 128, BB);
    proj_kernel<<<pg, 256>>>(src_emb, Wq, bq, 0);
    proj_kernel<<<pg, 256>>>(tgt_emb, Wk, bk, 1);
    kk_kernel<<<BB * MM / 8, 256>>>();

    const int smem_bytes = (EE * 64 + 32 * 128 + 128 + 384) * sizeof(float);
    cudaFuncSetAttribute(attn_kernel, cudaFuncAttributeMaxDynamicSharedMemorySize,
                         smem_bytes);
    attn_kernel<<<dim3(NN / 64, BB), 256, smem_bytes>>>(tgt, corr_out);

    if (tuple_out)
        copy_src_kernel<<<(corr_elems + 255) / 256, 256>>>(src, out);
}

// round 2
// speedup vs baseline: 1.3313x; 1.3313x over previous
#include <cuda_runtime.h>
#include <math.h>

#define BB 2
#define EE 512
#define NN 4096
#define MM 4096

typedef unsigned long long u64;

// Scratch (static __device__ — allocation-free per harness rules)
__device__ float g_Q[BB * EE * NN];   // Qt: [b][f][n]  16 MB
__device__ float g_K[BB * EE * MM];   // Kt: [b][f][m]  16 MB
__device__ float g_kk[BB * MM];       // ||k||^2

// ---- packed f32x2 helpers (sm_100+ PTX) -----------------------------------
__device__ __forceinline__ u64 pack2(float x) {
    u64 r; asm("mov.b64 %0, {%1, %1};" : "=l"(r) : "f"(x)); return r;
}
__device__ __forceinline__ void fma2(u64& d, u64 a, u64 b) {
    asm("fma.rn.f32x2 %0, %1, %2, %3;" : "=l"(d) : "l"(a), "l"(b), "l"(d));
}
__device__ __forceinline__ float2 unpack2(u64 v) {
    float2 f; asm("mov.b64 {%0, %1}, %2;" : "=f"(f.x), "=f"(f.y) : "l"(v)); return f;
}

// ---------------------------------------------------------------------------
// Projection: Yt[b][f][n] = sum_e X[b][e][n] * W[f][e] + bias[f]   (transposed out)
// Block tile 64(n) x 128(f), 256 threads, per-thread 4x8 (f in fma2 pairs).
// ---------------------------------------------------------------------------
__global__ __launch_bounds__(256) void proj_kernel(
    const float* __restrict__ X, const float* __restrict__ W,
    const float* __restrict__ bias, int which)
{
    float* __restrict__ Y = which ? g_K : g_Q;
    __shared__ float Xs[32][64];    // [e][n]
    __shared__ float Ws[32][128];   // [e][f]

    const int tid = threadIdx.x;
    const int tx = tid & 15, ty = tid >> 4;
    const int n0 = blockIdx.x * 64;
    const int f0 = blockIdx.y * 128;
    const int b  = blockIdx.z;

    u64 acc[4][4];
#pragma unroll
    for (int i = 0; i < 4; ++i)
#pragma unroll
        for (int j = 0; j < 4; ++j) acc[i][j] = 0ull;

    const float* Xb = X + (size_t)b * EE * NN;

    for (int e0 = 0; e0 < EE; e0 += 32) {
        {   // Xs: 32 e-rows x 64 n-cols, direct copy
            const int r = tid >> 3;
            const int c = (tid & 7) * 8;
            const float4* s4 = (const float4*)(Xb + (size_t)(e0 + r) * NN + n0 + c);
            float4 v0 = s4[0], v1 = s4[1];
            *(float4*)&Xs[r][c]     = v0;
            *(float4*)&Xs[r][c + 4] = v1;
        }
        {   // Ws: transpose 128 f-rows x 32 e-cols -> [e][f]
            const int f  = tid >> 1;
            const int eo = (tid & 1) * 16;
            const float4* w4 = (const float4*)(W + (size_t)(f0 + f) * EE + e0 + eo);
#pragma unroll
            for (int k = 0; k < 4; ++k) {
                float4 v = w4[k];
                Ws[eo + 4 * k + 0][f] = v.x;
                Ws[eo + 4 * k + 1][f] = v.y;
                Ws[eo + 4 * k + 2][f] = v.z;
                Ws[eo + 4 * k + 3][f] = v.w;
            }
        }
        __syncthreads();
#pragma unroll 8
        for (int e = 0; e < 32; ++e) {
            float4 a = *(const float4*)&Xs[e][ty * 4];
            ulonglong2 b0 = *(const ulonglong2*)&Ws[e][tx * 4];
            ulonglong2 b1 = *(const ulonglong2*)&Ws[e][64 + tx * 4];
            u64 ap;
            ap = pack2(a.x);
            fma2(acc[0][0], ap, b0.x); fma2(acc[0][1], ap, b0.y);
            fma2(acc[0][2], ap, b1.x); fma2(acc[0][3], ap, b1.y);
            ap = pack2(a.y);
            fma2(acc[1][0], ap, b0.x); fma2(acc[1][1], ap, b0.y);
            fma2(acc[1][2], ap, b1.x); fma2(acc[1][3], ap, b1.y);
            ap = pack2(a.z);
            fma2(acc[2][0], ap, b0.x); fma2(acc[2][1], ap, b0.y);
            fma2(acc[2][2], ap, b1.x); fma2(acc[2][3], ap, b1.y);
            ap = pack2(a.w);
            fma2(acc[3][0], ap, b0.x); fma2(acc[3][1], ap, b0.y);
            fma2(acc[3][2], ap, b1.x); fma2(acc[3][3], ap, b1.y);
        }
        __syncthreads();
    }

    // epilogue: unpack, add bias, transposed store (f-major rows, n-contiguous)
    float v[4][8];
#pragma unroll
    for (int i = 0; i < 4; ++i) {
        float2 p;
        p = unpack2(acc[i][0]); v[i][0] = p.x; v[i][1] = p.y;
        p = unpack2(acc[i][1]); v[i][2] = p.x; v[i][3] = p.y;
        p = unpack2(acc[i][2]); v[i][4] = p.x; v[i][5] = p.y;
        p = unpack2(acc[i][3]); v[i][6] = p.x; v[i][7] = p.y;
    }
    float4 bs0 = *(const float4*)(bias + f0 + tx * 4);
    float4 bs1 = *(const float4*)(bias + f0 + 64 + tx * 4);
    float bv[8] = {bs0.x, bs0.y, bs0.z, bs0.w, bs1.x, bs1.y, bs1.z, bs1.w};
#pragma unroll
    for (int j = 0; j < 8; ++j) {
        const int f = (j < 4) ? (tx * 4 + j) : (64 + tx * 4 + (j - 4));
        float4 o = make_float4(v[0][j] + bv[j], v[1][j] + bv[j],
                               v[2][j] + bv[j], v[3][j] + bv[j]);
        *(float4*)(Y + ((size_t)b * EE + f0 + f) * NN + n0 + ty * 4) = o;
    }
}

// ---------------------------------------------------------------------------
// kk[b][m] = sum_f Kt[b][f][m]^2   (coalesced column sums over Kt)
// ---------------------------------------------------------------------------
__global__ __launch_bounds__(256) void kk_kernel()
{
    const int idx = blockIdx.x * 256 + threadIdx.x;   // over BB*MM
    const int b = idx >> 12;       // MM = 4096
    const int m = idx & (MM - 1);
    const float* p = g_K + (size_t)b * EE * MM + m;
    float s = 0.f;
#pragma unroll 8
    for (int f = 0; f < EE; ++f) {
        float v = p[(size_t)f * MM];
        s = fmaf(v, v, s);
    }
    g_kk[idx] = s;
}

// ---------------------------------------------------------------------------
// Flash attention: logits = 2 Q K^T - kk, online softmax, O = scores @ tgt^T
// CTA tile 64(n) x 256(m); 256 threads, per-thread 8x8 (m in fma2 pairs).
// Q tile (512x64) resident in SMEM; K streamed 32-e chunks, smem double-buffered.
// ---------------------------------------------------------------------------
__global__ __launch_bounds__(256, 1) void attn_kernel(
    const float* __restrict__ tgt, float* __restrict__ out_corr)
{
    extern __shared__ float sm[];
    float* Qs   = sm;                        // [512][64]
    float* Ks   = sm + EE * 64;              // [2][32][256]
    float* kks  = Ks + 2 * 32 * 256;         // [256]
    float* tgts = kks + 256;                 // [3][256]

    const int tid = threadIdx.x;
    const int tx = tid & 31, ty = tid >> 5;  // tx: m (8 cols), ty: n (8 rows)
    const int n0 = blockIdx.x * 64;
    const int b  = blockIdx.y;

    // Load Q tile (rows e, cols n) — straight copy from transposed Qt
    {
        const float* Qb = g_Q + (size_t)b * EE * NN + n0;
        const int r0 = tid >> 2;             // 0..63
        const int c4 = (tid & 3) * 4;        // float4 index
#pragma unroll
        for (int rr = 0; rr < EE; rr += 64) {
            const float4* s4 = (const float4*)(Qb + (size_t)(rr + r0) * NN) + c4;
            float4* d4 = (float4*)(Qs + (rr + r0) * 64) + c4;
            d4[0] = s4[0]; d4[1] = s4[1]; d4[2] = s4[2]; d4[3] = s4[3];
        }
    }

    float st_m[8], st_l[8], st_o[8][3];
#pragma unroll
    for (int i = 0; i < 8; ++i) {
        st_m[i] = -1e30f; st_l[i] = 0.f;
        st_o[i][0] = st_o[i][1] = st_o[i][2] = 0.f;
    }

    const float* Kb   = g_K + (size_t)b * EE * MM;
    const float* kkb  = g_kk + b * MM;
    const float* tgtb = tgt + (size_t)b * 3 * MM;

    // fill indexing: 8 threads per e-row, 8 float4 each
    const int fr = tid >> 3;                 // e-row 0..31
    const int fc = tid & 7;                  // float4 slot

    for (int m0 = 0; m0 < MM; m0 += 256) {
        __syncthreads();                     // prior tile's softmax done reading kks/tgts
        if (tid < 256) kks[tid] = kkb[m0 + tid];
        for (int t = tid; t < 768; t += 256)
            tgts[t] = tgtb[(t >> 8) * MM + m0 + (t & 255)];
        // fill chunk 0 -> buf 0
        {
            const float4* s4 = (const float4*)(Kb + (size_t)fr * MM + m0) + fc;
            float4* d4 = (float4*)(Ks + fr * 256) + fc;
            float4 tmp[8];
#pragma unroll
            for (int k = 0; k < 8; ++k) tmp[k] = s4[8 * k];
#pragma unroll
            for (int k = 0; k < 8; ++k) d4[8 * k] = tmp[k];
        }
        __syncthreads();

        u64 acc[8][4];
#pragma unroll
        for (int i = 0; i < 8; ++i)
#pragma unroll
            for (int j = 0; j < 4; ++j) acc[i][j] = 0ull;

        for (int c = 0; c < 16; ++c) {
            if (c < 15) {   // fill chunk c+1 into the other buffer
                const float* buf = Ks + ((c + 1) & 1) * (32 * 256);
                const float4* s4 = (const float4*)(Kb + (size_t)((c + 1) * 32 + fr) * MM + m0) + fc;
                float4* d4 = (float4*)(buf + fr * 256) + fc;
                float4 tmp[8];
#pragma unroll
                for (int k = 0; k < 8; ++k) tmp[k] = s4[8 * k];
#pragma unroll
                for (int k = 0; k < 8; ++k) d4[8 * k] = tmp[k];
            }
            const float* buf = Ks + (c & 1) * (32 * 256);
#pragma unroll 4
            for (int e = 0; e < 32; ++e) {
                const float* qrow = Qs + (c * 32 + e) * 64 + ty * 8;
                float4 a0 = *(const float4*)qrow;
                float4 a1 = *(const float4*)(qrow + 4);
                const float* krow = buf + e * 256;
                ulonglong2 kb0 = *(const ulonglong2*)(krow + tx * 4);
                ulonglong2 kb1 = *(const ulonglong2*)(krow + 128 + tx * 4);
                u64 ap;
                ap = pack2(a0.x);
                fma2(acc[0][0], ap, kb0.x); fma2(acc[0][1], ap, kb0.y);
                fma2(acc[0][2], ap, kb1.x); fma2(acc[0][3], ap, kb1.y);
                ap = pack2(a0.y);
                fma2(acc[1][0], ap, kb0.x); fma2(acc[1][1], ap, kb0.y);
                fma2(acc[1][2], ap, kb1.x); fma2(acc[1][3], ap, kb1.y);
                ap = pack2(a0.z);
                fma2(acc[2][0], ap, kb0.x); fma2(acc[2][1], ap, kb0.y);
                fma2(acc[2][2], ap, kb1.x); fma2(acc[2][3], ap, kb1.y);
                ap = pack2(a0.w);
                fma2(acc[3][0], ap, kb0.x); fma2(acc[3][1], ap, kb0.y);
                fma2(acc[3][2], ap, kb1.x); fma2(acc[3][3], ap, kb1.y);
                ap = pack2(a1.x);
                fma2(acc[4][0], ap, kb0.x); fma2(acc[4][1], ap, kb0.y);
                fma2(acc[4][2], ap, kb1.x); fma2(acc[4][3], ap, kb1.y);
                ap = pack2(a1.y);
                fma2(acc[5][0], ap, kb0.x); fma2(acc[5][1], ap, kb0.y);
                fma2(acc[5][2], ap, kb1.x); fma2(acc[5][3], ap, kb1.y);
                ap = pack2(a1.z);
                fma2(acc[6][0], ap, kb0.x); fma2(acc[6][1], ap, kb0.y);
                fma2(acc[6][2], ap, kb1.x); fma2(acc[6][3], ap, kb1.y);
                ap = pack2(a1.w);
                fma2(acc[7][0], ap, kb0.x); fma2(acc[7][1], ap, kb0.y);
                fma2(acc[7][2], ap, kb1.x); fma2(acc[7][3], ap, kb1.y);
            }
            __syncthreads();
        }

        // Online softmax update for this 256-m tile (8 m-cols per thread)
        float4 kk0 = *(const float4*)&kks[tx * 4];
        float4 kk1 = *(const float4*)&kks[128 + tx * 4];
        float4 t00 = *(const float4*)&tgts[tx * 4];
        float4 t01 = *(const float4*)&tgts[128 + tx * 4];
        float4 t10 = *(const float4*)&tgts[256 + tx * 4];
        float4 t11 = *(const float4*)&tgts[256 + 128 + tx * 4];
        float4 t20 = *(const float4*)&tgts[512 + tx * 4];
        float4 t21 = *(const float4*)&tgts[512 + 128 + tx * 4];
#pragma unroll
        for (int i = 0; i < 8; ++i) {
            float lg[8]; float2 p;
            p = unpack2(acc[i][0]); lg[0] = 2.f * p.x - kk0.x; lg[1] = 2.f * p.y - kk0.y;
            p = unpack2(acc[i][1]); lg[2] = 2.f * p.x - kk0.z; lg[3] = 2.f * p.y - kk0.w;
            p = unpack2(acc[i][2]); lg[4] = 2.f * p.x - kk1.x; lg[5] = 2.f * p.y - kk1.y;
            p = unpack2(acc[i][3]); lg[6] = 2.f * p.x - kk1.z; lg[7] = 2.f * p.y - kk1.w;
            float lmax = lg[0];
#pragma unroll
            for (int j = 1; j < 8; ++j) lmax = fmaxf(lmax, lg[j]);
            const float nm = fmaxf(st_m[i], lmax);
            const float sc = __expf(st_m[i] - nm);
            st_l[i] *= sc;
            st_o[i][0] *= sc; st_o[i][1] *= sc; st_o[i][2] *= sc;
            float pj[8];
#pragma unroll
            for (int j = 0; j < 8; ++j) pj[j] = __expf(lg[j] - nm);
#pragma unroll
            for (int j = 0; j < 8; ++j) st_l[i] += pj[j];
            st_o[i][0] += pj[0]*t00.x + pj[1]*t00.y + pj[2]*t00.z + pj[3]*t00.w
                        + pj[4]*t01.x + pj[5]*t01.y + pj[6]*t01.z + pj[7]*t01.w;
            st_o[i][1] += pj[0]*t10.x + pj[1]*t10.y + pj[2]*t10.z + pj[3]*t10.w
                        + pj[4]*t11.x + pj[5]*t11.y + pj[6]*t11.z + pj[7]*t11.w;
            st_o[i][2] += pj[0]*t20.x + pj[1]*t20.y + pj[2]*t20.z + pj[3]*t20.w
                        + pj[4]*t21.x + pj[5]*t21.y + pj[6]*t21.z + pj[7]*t21.w;
            st_m[i] = nm;
        }
    }

    // Merge the 32 per-row partial states across the warp (m dimension)
#pragma unroll
    for (int i = 0; i < 8; ++i) {
        float m = st_m[i], l = st_l[i];
        float o0 = st_o[i][0], o1 = st_o[i][1], o2 = st_o[i][2];
#pragma unroll
        for (int off = 16; off; off >>= 1) {
            float om = __shfl_xor_sync(0xffffffffu, m,  off);
            float ol = __shfl_xor_sync(0xffffffffu, l,  off);
            float p0 = __shfl_xor_sync(0xffffffffu, o0, off);
            float p1 = __shfl_xor_sync(0xffffffffu, o1, off);
            float p2 = __shfl_xor_sync(0xffffffffu, o2, off);
            const float nm = fmaxf(m, om);
            const float sa = __expf(m - nm);
            const float sb = __expf(om - nm);
            l  = l  * sa + ol * sb;
            o0 = o0 * sa + p0 * sb;
            o1 = o1 * sa + p1 * sb;
            o2 = o2 * sa + p2 * sb;
            m = nm;
        }
        if (tx == 0) {
            const int n = n0 + ty * 8 + i;
            const float inv = 1.f / l;
            out_corr[((size_t)b * 3 + 0) * NN + n] = o0 * inv;
            out_corr[((size_t)b * 3 + 1) * NN + n] = o1 * inv;
            out_corr[((size_t)b * 3 + 2) * NN + n] = o2 * inv;
        }
    }
}

// ---------------------------------------------------------------------------
__global__ void copy_src_kernel(const float* __restrict__ src, float* __restrict__ out)
{
    const int i = blockIdx.x * 256 + threadIdx.x;
    if (i < BB * 3 * NN) out[i] = src[i];
}

// ---------------------------------------------------------------------------
extern "C" void kernel_launch(void* const* d_in, const int* in_sizes, int n_in,
                              void* d_out, int out_size)
{
    const float* src_emb = (const float*)d_in[0];
    const float* tgt_emb = (const float*)d_in[1];
    const float* src     = (const float*)d_in[2];
    const float* tgt     = (const float*)d_in[3];
    const float* Wq      = (const float*)d_in[4];
    const float* bq      = (const float*)d_in[5];
    const float* Wk      = (const float*)d_in[6];
    const float* bk      = (const float*)d_in[7];
    float* out = (float*)d_out;

    const int corr_elems = BB * 3 * NN;
    const bool tuple_out = (out_size >= 2 * corr_elems);
    float* corr_out = tuple_out ? (out + corr_elems) : out;

    dim3 pg(NN / 64, EE / 128, BB);
    proj_kernel<<<pg, 256>>>(src_emb, Wq, bq, 0);
    proj_kernel<<<pg, 256>>>(tgt_emb, Wk, bk, 1);
    kk_kernel<<<BB * MM / 256, 256>>>();

    const int smem_bytes = (EE * 64 + 2 * 32 * 256 + 256 + 768) * sizeof(float);
    cudaFuncSetAttribute(attn_kernel, cudaFuncAttributeMaxDynamicSharedMemorySize,
                         smem_bytes);
    attn_kernel<<<dim3(NN / 64, BB), 256, smem_bytes>>>(tgt, corr_out);

    if (tuple_out)
        copy_src_kernel<<<(corr_elems + 255) / 256, 256>>>(src, out);
}